// round 11
// baseline (speedup 1.0000x reference)
#include <cuda_runtime.h>
#include <cuda_bf16.h>
#include <cstdint>

typedef __nv_bfloat16 bf16;

#define S_LEN 2048
#define HID   4096
#define NH    32
#define NKV   8
#define HD    128

// ---------------- scratch (static device globals; no allocation) -------------
__device__ __align__(256) float g_qlin[(size_t)S_LEN * HID];
__device__ __align__(256) float g_klin[(size_t)S_LEN * (NKV * HD)];
__device__ __align__(256) float g_vlin[(size_t)S_LEN * (NKV * HD)];

// split-bf16 buffers
__device__ __align__(256) bf16 g_hid_hi[(size_t)S_LEN * HID];
__device__ __align__(256) bf16 g_hid_lo[(size_t)S_LEN * HID];
__device__ __align__(256) bf16 g_wq_hi[(size_t)HID * HID];
__device__ __align__(256) bf16 g_wq_lo[(size_t)HID * HID];
__device__ __align__(256) bf16 g_wk_hi[(size_t)(NKV * HD) * HID];
__device__ __align__(256) bf16 g_wk_lo[(size_t)(NKV * HD) * HID];
__device__ __align__(256) bf16 g_wv_hi[(size_t)(NKV * HD) * HID];
__device__ __align__(256) bf16 g_wv_lo[(size_t)(NKV * HD) * HID];
__device__ __align__(256) bf16 g_wo_hi[(size_t)HID * HID];
__device__ __align__(256) bf16 g_wo_lo[(size_t)HID * HID];
__device__ __align__(256) bf16 g_attn_hi[(size_t)S_LEN * HID];
__device__ __align__(256) bf16 g_attn_lo[(size_t)S_LEN * HID];

// attention operands (hi/lo bf16)
__device__ __align__(256) bf16 g_qh[(size_t)NH * S_LEN * HD];
__device__ __align__(256) bf16 g_ql[(size_t)NH * S_LEN * HD];
__device__ __align__(256) bf16 g_kh[(size_t)NKV * S_LEN * HD];
__device__ __align__(256) bf16 g_kl[(size_t)NKV * S_LEN * HD];
__device__ __align__(256) bf16 g_vth[(size_t)NKV * HD * S_LEN];   // [kvh*128+d][s]
__device__ __align__(256) bf16 g_vtl[(size_t)NKV * HD * S_LEN];

// ============================= helpers ======================================
__device__ __forceinline__ uint32_t smem_u32(const void* p) {
    uint32_t a;
    asm("{ .reg .u64 t; cvta.to.shared.u64 t, %1; cvt.u32.u64 %0, t; }"
        : "=r"(a) : "l"(p));
    return a;
}

#define SW128(o) ((o) ^ (((o) >> 3) & 0x70))

__device__ __forceinline__ void cpasync16(uint32_t dst, const void* src) {
    asm volatile("cp.async.cg.shared.global [%0], [%1], 16;"
                 :: "r"(dst), "l"(src));
}

#define LDSM4(r0, r1, r2, r3, a)                                              \
    asm volatile("ldmatrix.sync.aligned.m8n8.x4.shared.b16 {%0,%1,%2,%3}, [%4];" \
        : "=r"(r0), "=r"(r1), "=r"(r2), "=r"(r3) : "r"(a))

#define MMA16816(d, a0, a1, a2, a3, b0, b1)                                   \
    asm volatile("mma.sync.aligned.m16n8k16.row.col.f32.bf16.bf16.f32 "       \
        "{%0,%1,%2,%3}, {%4,%5,%6,%7}, {%8,%9}, {%0,%1,%2,%3};"               \
        : "+f"((d)[0]), "+f"((d)[1]), "+f"((d)[2]), "+f"((d)[3])              \
        : "r"(a0), "r"(a1), "r"(a2), "r"(a3), "r"(b0), "r"(b1))

__device__ __forceinline__ uint32_t pack2(bf16 a, bf16 b) {
    __nv_bfloat162 t = __halves2bfloat162(a, b);
    return *reinterpret_cast<uint32_t*>(&t);
}

__device__ __forceinline__ void psplit(float a, float b, uint32_t& hi, uint32_t& lo) {
    bf16 ha = __float2bfloat16(a), hb = __float2bfloat16(b);
    float ra = a - __bfloat162float(ha), rb = b - __bfloat162float(hb);
    hi = pack2(ha, hb);
    lo = pack2(__float2bfloat16(ra), __float2bfloat16(rb));
}

// ============================================================================
// fp32 -> (bf16 hi, bf16 lo) split conversion, vectorized x4
// ============================================================================
__global__ __launch_bounds__(256) void cvt_hilo(
    const float4* __restrict__ x, __nv_bfloat162* __restrict__ hi,
    __nv_bfloat162* __restrict__ lo, int n4)
{
    int i = blockIdx.x * 256 + threadIdx.x;
    if (i >= n4) return;
    float4 v = x[i];
    bf16 h0 = __float2bfloat16(v.x), h1 = __float2bfloat16(v.y);
    bf16 h2 = __float2bfloat16(v.z), h3 = __float2bfloat16(v.w);
    bf16 l0 = __float2bfloat16(v.x - __bfloat162float(h0));
    bf16 l1 = __float2bfloat16(v.y - __bfloat162float(h1));
    bf16 l2 = __float2bfloat16(v.z - __bfloat162float(h2));
    bf16 l3 = __float2bfloat16(v.w - __bfloat162float(h3));
    hi[2 * i]     = __halves2bfloat162(h0, h1);
    hi[2 * i + 1] = __halves2bfloat162(h2, h3);
    lo[2 * i]     = __halves2bfloat162(l0, l1);
    lo[2 * i + 1] = __halves2bfloat162(l2, l3);
}

// ============================================================================
// V transpose + split: vlin [S][1024] fp32 -> vt_hi/lo [kvh*128+d][S] bf16
// ============================================================================
__global__ __launch_bounds__(256) void vt_cvt(
    const float* __restrict__ v, bf16* __restrict__ th, bf16* __restrict__ tl)
{
    __shared__ float t[32][33];
    int s0 = blockIdx.x * 32, c0 = blockIdx.y * 32;
    int tx = threadIdx.x, ty = threadIdx.y;
    #pragma unroll
    for (int r = 0; r < 4; r++)
        t[ty + r * 8][tx] = v[(size_t)(s0 + ty + r * 8) * (NKV * HD) + c0 + tx];
    __syncthreads();
    #pragma unroll
    for (int r = 0; r < 4; r++) {
        int gc = c0 + ty + r * 8;
        float val = t[tx][ty + r * 8];
        bf16 hh = __float2bfloat16(val);
        bf16 ll = __float2bfloat16(val - __bfloat162float(hh));
        th[(size_t)gc * S_LEN + s0 + tx] = hh;
        tl[(size_t)gc * S_LEN + s0 + tx] = ll;
    }
}

// ============================================================================
// HMMA split-bf16 GEMM: 3-stage cp.async pipeline, single sync per iter.
// CTA 128x128, BK=64, 8 warps (2x4), warp tile 64x32, SW128 smem.
// ============================================================================
#define GS_A  16384u
#define GSTG  65536u
#define GEMM_SMEM_BYTES (3 * 65536)

__global__ __launch_bounds__(256) void hmma_gemm(
    const bf16* __restrict__ Ah, const bf16* __restrict__ Al,
    const bf16* __restrict__ Bh, const bf16* __restrict__ Bl,
    float* __restrict__ C, int M, int N, int K)
{
    extern __shared__ char smc[];
    uint32_t sb = smem_u32(smc);

    int tid = threadIdx.x;
    int wid = tid >> 5, lane = tid & 31;
    int mbase = blockIdx.y * 128, nbase = blockIdx.x * 128;
    int warpM = (wid & 1) * 64;
    int warpN = (wid >> 1) * 32;

    const bf16* Aho = Ah + (size_t)mbase * K;
    const bf16* Alo = Al + (size_t)mbase * K;
    const bf16* Bho = Bh + (size_t)nbase * K;
    const bf16* Blo = Bl + (size_t)nbase * K;

    const int KT = K >> 6;

    auto load_stage = [&](int s, int kt) {
        uint32_t sa = sb + (uint32_t)s * GSTG;
        int kb = kt << 6;
        #pragma unroll
        for (int i = 0; i < 4; i++) {
            int idx = tid + i * 256;
            int row = idx >> 3;
            int c8 = idx & 7;
            uint32_t off = SW128((uint32_t)(row * 128 + c8 * 16));
            size_t g = (size_t)row * K + kb + c8 * 8;
            cpasync16(sa + off,              Aho + g);
            cpasync16(sa + GS_A + off,       Alo + g);
            cpasync16(sa + 2 * GS_A + off,   Bho + g);
            cpasync16(sa + 3 * GS_A + off,   Blo + g);
        }
        asm volatile("cp.async.commit_group;" ::: "memory");
    };

    float acc[4][4][4];
    #pragma unroll
    for (int a = 0; a < 4; a++)
        #pragma unroll
        for (int b = 0; b < 4; b++)
            #pragma unroll
            for (int c = 0; c < 4; c++) acc[a][b][c] = 0.f;

    // prologue: 2 stages in flight
    load_stage(0, 0);
    load_stage(1, 1);

    uint32_t lrow = lane & 15;
    uint32_t lcsel = (lane >> 4) * 16;

    for (int kt = 0; kt < KT; kt++) {
        // drain group kt (last iter: nothing newer pending -> drain all)
        if (kt + 1 < KT) {
            asm volatile("cp.async.wait_group 1;" ::: "memory");
        } else {
            asm volatile("cp.async.wait_group 0;" ::: "memory");
        }
        __syncthreads();
        // issue kt+2 into buffer last read at iter kt-1 (all warps past sync)
        if (kt + 2 < KT) load_stage((kt + 2) % 3, kt + 2);

        uint32_t st = sb + (uint32_t)(kt % 3) * GSTG;
        #pragma unroll
        for (int kk = 0; kk < 4; kk++) {
            uint32_t acol = kk * 32 + lcsel;
            uint32_t ah4[4][4], al4[4][4];
            #pragma unroll
            for (int mi = 0; mi < 4; mi++) {
                uint32_t off = SW128((uint32_t)((warpM + mi * 16 + lrow) * 128) + acol);
                LDSM4(ah4[mi][0], ah4[mi][1], ah4[mi][2], ah4[mi][3], st + off);
                LDSM4(al4[mi][0], al4[mi][1], al4[mi][2], al4[mi][3], st + GS_A + off);
            }
            uint32_t bh4[2][4], bl4[2][4];
            #pragma unroll
            for (int p = 0; p < 2; p++) {
                uint32_t off = SW128((uint32_t)((warpN + p * 16 + lrow) * 128) + acol);
                LDSM4(bh4[p][0], bh4[p][1], bh4[p][2], bh4[p][3], st + 2 * GS_A + off);
                LDSM4(bl4[p][0], bl4[p][1], bl4[p][2], bl4[p][3], st + 3 * GS_A + off);
            }
            #pragma unroll
            for (int mi = 0; mi < 4; mi++) {
                #pragma unroll
                for (int t = 0; t < 4; t++) {
                    int p = t >> 1, h = t & 1;
                    MMA16816(acc[mi][t], ah4[mi][0], ah4[mi][1], ah4[mi][2], ah4[mi][3],
                             bh4[p][h], bh4[p][h + 2]);
                    MMA16816(acc[mi][t], ah4[mi][0], ah4[mi][1], ah4[mi][2], ah4[mi][3],
                             bl4[p][h], bl4[p][h + 2]);
                    MMA16816(acc[mi][t], al4[mi][0], al4[mi][1], al4[mi][2], al4[mi][3],
                             bh4[p][h], bh4[p][h + 2]);
                }
            }
        }
    }

    #pragma unroll
    for (int mi = 0; mi < 4; mi++) {
        int row0 = mbase + warpM + mi * 16 + (lane >> 2);
        #pragma unroll
        for (int t = 0; t < 4; t++) {
            int col = nbase + warpN + t * 8 + (lane & 3) * 2;
            float2 v0 = { acc[mi][t][0], acc[mi][t][1] };
            float2 v1 = { acc[mi][t][2], acc[mi][t][3] };
            *(float2*)&C[(size_t)row0 * N + col] = v0;
            *(float2*)&C[(size_t)(row0 + 8) * N + col] = v1;
        }
    }
}

// =============================================================================
// Per-(s, head) RMSNorm + RoPE -> bf16 hi/lo head-major outputs
// =============================================================================
__global__ __launch_bounds__(128) void qk_norm_rope(
    const float* __restrict__ qlin, const float* __restrict__ klin,
    const float* __restrict__ qw, const float* __restrict__ kw,
    const int* __restrict__ pos_ids,
    const float* __restrict__ cosT, const float* __restrict__ sinT,
    bf16* __restrict__ qh, bf16* __restrict__ ql,
    bf16* __restrict__ kh, bf16* __restrict__ kl)
{
    int s = blockIdx.x;
    int hb = blockIdx.y;
    int i = threadIdx.x;

    float x;
    const float* w;
    bf16 *dh, *dl;
    size_t o;
    if (hb < NH) {
        x = qlin[(size_t)s * HID + hb * HD + i];
        w = qw;
        o = ((size_t)hb * S_LEN + s) * HD + i;
        dh = qh; dl = ql;
    } else {
        int hk = hb - NH;
        x = klin[(size_t)s * (NKV * HD) + hk * HD + i];
        w = kw;
        o = ((size_t)hk * S_LEN + s) * HD + i;
        dh = kh; dl = kl;
    }

    __shared__ float red[128];
    __shared__ float xs[128];
    __shared__ float s_inv;

    red[i] = x * x;
    __syncthreads();
    if (i < 64) red[i] += red[i + 64];
    __syncthreads();
    if (i < 32) {
        float v = red[i] + red[i + 32];
        #pragma unroll
        for (int of = 16; of > 0; of >>= 1) v += __shfl_xor_sync(0xffffffffu, v, of);
        if (i == 0) s_inv = rsqrtf(v * (1.0f / 128.0f) + 1e-6f);
    }
    __syncthreads();

    float xn = x * s_inv * w[i];
    xs[i] = xn;
    __syncthreads();
    float other = (i < 64) ? -xs[i + 64] : xs[i - 64];
    int p = pos_ids[s];
    float c = cosT[(size_t)p * HD + i];
    float sn = sinT[(size_t)p * HD + i];
    float r = xn * c + other * sn;
    bf16 hh = __float2bfloat16(r);
    dh[o] = hh;
    dl[o] = __float2bfloat16(r - __bfloat162float(hh));
}

// =============================================================================
// HMMA flash attention (split-bf16, causal, GQA 4:1)
// grid=(16 q-blocks REVERSED for load balance, 32 heads), 256 threads.
// =============================================================================
#define AT_SMEM 196608

__global__ __launch_bounds__(256) void attn_hmma(
    const bf16* __restrict__ Qh, const bf16* __restrict__ Ql,
    const bf16* __restrict__ Kh, const bf16* __restrict__ Kl,
    const bf16* __restrict__ Vh, const bf16* __restrict__ Vl,
    bf16* __restrict__ Oh, bf16* __restrict__ Ol)
{
    extern __shared__ char smc[];
    uint32_t sb = smem_u32(smc);
    const uint32_t QHo = 0, QLo = 32768, STG0 = 65536, STGSZ = 65536;

    int h = blockIdx.y;
    int qb = gridDim.x - 1 - blockIdx.x;   // heavy (large qb) CTAs dispatch first
    int kvh = h >> 2;
    int qbase = qb * 128;
    int tid = threadIdx.x, wid = tid >> 5, lane = tid & 31;
    int warpM = wid * 16;

    // Q loads (bundled into first commit group with kv stage 0)
    const bf16* qhs = Qh + ((size_t)h * S_LEN + qbase) * HD;
    const bf16* qls = Ql + ((size_t)h * S_LEN + qbase) * HD;
    #pragma unroll
    for (int i = 0; i < 8; i++) {
        int idx = tid + i * 256;
        int c = idx >> 10, rem = idx & 1023;
        int row = rem >> 3, c8 = rem & 7;
        uint32_t off = (uint32_t)c * 16384u + SW128((uint32_t)(row * 128 + c8 * 16));
        size_t g = (size_t)row * HD + c * 64 + c8 * 8;
        cpasync16(sb + QHo + off, qhs + g);
        cpasync16(sb + QLo + off, qls + g);
    }

    auto load_kv = [&](int st, int kt) {
        uint32_t sa = sb + STG0 + (uint32_t)st * STGSZ;
        int n0 = kt * 64;
        const bf16* khs = Kh + ((size_t)kvh * S_LEN + n0) * HD;
        const bf16* kls = Kl + ((size_t)kvh * S_LEN + n0) * HD;
        #pragma unroll
        for (int i = 0; i < 4; i++) {
            int idx = tid + i * 256;
            int c = idx >> 9, row = (idx >> 3) & 63, c8 = idx & 7;
            uint32_t off = (uint32_t)c * 8192u + SW128((uint32_t)(row * 128 + c8 * 16));
            size_t g = (size_t)row * HD + c * 64 + c8 * 8;
            cpasync16(sa + off, khs + g);
            cpasync16(sa + 16384u + off, kls + g);
        }
        const bf16* vhs = Vh + (size_t)kvh * HD * S_LEN + n0;
        const bf16* vls = Vl + (size_t)kvh * HD * S_LEN + n0;
        #pragma unroll
        for (int i = 0; i < 4; i++) {
            int idx = tid + i * 256;
            int row = idx >> 3, c8 = idx & 7;
            uint32_t off = SW128((uint32_t)(row * 128 + c8 * 16));
            size_t g = (size_t)row * S_LEN + c8 * 8;
            cpasync16(sa + 32768u + off, vhs + g);
            cpasync16(sa + 49152u + off, vls + g);
        }
        asm volatile("cp.async.commit_group;" ::: "memory");
    };

    load_kv(0, 0);

    float acc_o[16][4];
    #pragma unroll
    for (int n = 0; n < 16; n++)
        #pragma unroll
        for (int c = 0; c < 4; c++) acc_o[n][c] = 0.f;
    float m0 = -1e30f, m1 = -1e30f, l0 = 0.f, l1 = 0.f;

    int nkt = 2 * (qb + 1);
    const float scale = 0.08838834764831845f;
    uint32_t lrow = lane & 15, lcsel = (lane >> 4) * 16;
    int rowg0 = qbase + warpM + (lane >> 2);

    for (int kt = 0; kt < nkt; kt++) {
        asm volatile("cp.async.wait_group 0;" ::: "memory");
        __syncthreads();
        if (kt + 1 < nkt) load_kv((kt + 1) & 1, kt + 1);

        uint32_t sa = sb + STG0 + (uint32_t)(kt & 1) * STGSZ;
        int n0 = kt * 64;

        // ---- S = Q K^T (3-term split)
        float acc_s[8][4];
        #pragma unroll
        for (int n = 0; n < 8; n++)
            #pragma unroll
            for (int c = 0; c < 4; c++) acc_s[n][c] = 0.f;

        #pragma unroll
        for (int c = 0; c < 2; c++) {
            #pragma unroll
            for (int kk = 0; kk < 4; kk++) {
                uint32_t aoff = (uint32_t)c * 16384u +
                    SW128((uint32_t)((warpM + lrow) * 128) + kk * 32 + lcsel);
                uint32_t aH[4], aL[4];
                LDSM4(aH[0], aH[1], aH[2], aH[3], sb + QHo + aoff);
                LDSM4(aL[0], aL[1], aL[2], aL[3], sb + QLo + aoff);
                #pragma unroll
                for (int kg = 0; kg < 4; kg++) {
                    uint32_t boff = (uint32_t)c * 8192u +
                        SW128((uint32_t)((kg * 16 + lrow) * 128) + kk * 32 + lcsel);
                    uint32_t bH[4], bL[4];
                    LDSM4(bH[0], bH[1], bH[2], bH[3], sa + boff);
                    LDSM4(bL[0], bL[1], bL[2], bL[3], sa + 16384u + boff);
                    #pragma unroll
                    for (int hh = 0; hh < 2; hh++) {
                        int nt = kg * 2 + hh;
                        MMA16816(acc_s[nt], aH[0], aH[1], aH[2], aH[3], bH[hh], bH[hh + 2]);
                        MMA16816(acc_s[nt], aH[0], aH[1], aH[2], aH[3], bL[hh], bL[hh + 2]);
                        MMA16816(acc_s[nt], aL[0], aL[1], aL[2], aL[3], bH[hh], bH[hh + 2]);
                    }
                }
            }
        }

        // ---- scale + causal mask
        bool anymask = (n0 + 64 > qbase + warpM);
        #pragma unroll
        for (int nt = 0; nt < 8; nt++) {
            #pragma unroll
            for (int c = 0; c < 4; c++) acc_s[nt][c] *= scale;
        }
        if (anymask) {
            #pragma unroll
            for (int nt = 0; nt < 8; nt++) {
                int colb = n0 + nt * 8 + (lane & 3) * 2;
                if (colb > rowg0)         acc_s[nt][0] = -1e30f;
                if (colb + 1 > rowg0)     acc_s[nt][1] = -1e30f;
                if (colb > rowg0 + 8)     acc_s[nt][2] = -1e30f;
                if (colb + 1 > rowg0 + 8) acc_s[nt][3] = -1e30f;
            }
        }

        // ---- online softmax
        float mx0 = -1e30f, mx1 = -1e30f;
        #pragma unroll
        for (int nt = 0; nt < 8; nt++) {
            mx0 = fmaxf(mx0, fmaxf(acc_s[nt][0], acc_s[nt][1]));
            mx1 = fmaxf(mx1, fmaxf(acc_s[nt][2], acc_s[nt][3]));
        }
        mx0 = fmaxf(mx0, __shfl_xor_sync(0xffffffffu, mx0, 1));
        mx0 = fmaxf(mx0, __shfl_xor_sync(0xffffffffu, mx0, 2));
        mx1 = fmaxf(mx1, __shfl_xor_sync(0xffffffffu, mx1, 1));
        mx1 = fmaxf(mx1, __shfl_xor_sync(0xffffffffu, mx1, 2));
        float mn0 = fmaxf(m0, mx0), mn1 = fmaxf(m1, mx1);
        float al0 = __expf(m0 - mn0), al1 = __expf(m1 - mn1);

        float s0 = 0.f, s1 = 0.f;
        #pragma unroll
        for (int nt = 0; nt < 8; nt++) {
            acc_s[nt][0] = __expf(acc_s[nt][0] - mn0);
            acc_s[nt][1] = __expf(acc_s[nt][1] - mn0);
            acc_s[nt][2] = __expf(acc_s[nt][2] - mn1);
            acc_s[nt][3] = __expf(acc_s[nt][3] - mn1);
            s0 += acc_s[nt][0] + acc_s[nt][1];
            s1 += acc_s[nt][2] + acc_s[nt][3];
        }
        s0 += __shfl_xor_sync(0xffffffffu, s0, 1);
        s0 += __shfl_xor_sync(0xffffffffu, s0, 2);
        s1 += __shfl_xor_sync(0xffffffffu, s1, 1);
        s1 += __shfl_xor_sync(0xffffffffu, s1, 2);
        l0 = l0 * al0 + s0; m0 = mn0;
        l1 = l1 * al1 + s1; m1 = mn1;

        // ---- pack P into PV A-fragments (registers only)
        uint32_t paH[4][4], paL[4][4];
        #pragma unroll
        for (int k2 = 0; k2 < 4; k2++) {
            int a = 2 * k2, b = 2 * k2 + 1;
            psplit(acc_s[a][0], acc_s[a][1], paH[k2][0], paL[k2][0]);
            psplit(acc_s[a][2], acc_s[a][3], paH[k2][1], paL[k2][1]);
            psplit(acc_s[b][0], acc_s[b][1], paH[k2][2], paL[k2][2]);
            psplit(acc_s[b][2], acc_s[b][3], paH[k2][3], paL[k2][3]);
        }

        // ---- rescale O
        #pragma unroll
        for (int nt = 0; nt < 16; nt++) {
            acc_o[nt][0] *= al0; acc_o[nt][1] *= al0;
            acc_o[nt][2] *= al1; acc_o[nt][3] *= al1;
        }

        // ---- O += P V (3-term split)
        #pragma unroll
        for (int k2 = 0; k2 < 4; k2++) {
            #pragma unroll
            for (int dg = 0; dg < 8; dg++) {
                uint32_t boff = SW128((uint32_t)((dg * 16 + lrow) * 128) + k2 * 32 + lcsel);
                uint32_t bH[4], bL[4];
                LDSM4(bH[0], bH[1], bH[2], bH[3], sa + 32768u + boff);
                LDSM4(bL[0], bL[1], bL[2], bL[3], sa + 49152u + boff);
                #pragma unroll
                for (int hh = 0; hh < 2; hh++) {
                    int nt = dg * 2 + hh;
                    MMA16816(acc_o[nt], paH[k2][0], paH[k2][1], paH[k2][2], paH[k2][3],
                             bH[hh], bH[hh + 2]);
                    MMA16816(acc_o[nt], paH[k2][0], paH[k2][1], paH[k2][2], paH[k2][3],
                             bL[hh], bL[hh + 2]);
                    MMA16816(acc_o[nt], paL[k2][0], paL[k2][1], paL[k2][2], paL[k2][3],
                             bH[hh], bH[hh + 2]);
                }
            }
        }
    }

    // ---- epilogue: write bf16 hi/lo directly
    float inv0 = 1.0f / l0, inv1 = 1.0f / l1;
    #pragma unroll
    for (int nt = 0; nt < 16; nt++) {
        int col = h * HD + nt * 8 + (lane & 3) * 2;
        float v0 = acc_o[nt][0] * inv0, v1 = acc_o[nt][1] * inv0;
        float v2 = acc_o[nt][2] * inv1, v3 = acc_o[nt][3] * inv1;
        uint32_t hA, lA, hB, lB;
        psplit(v0, v1, hA, lA);
        psplit(v2, v3, hB, lB);
        size_t o0 = (size_t)rowg0 * HID + col;
        size_t o1 = (size_t)(rowg0 + 8) * HID + col;
        *(uint32_t*)&Oh[o0] = hA; *(uint32_t*)&Ol[o0] = lA;
        *(uint32_t*)&Oh[o1] = hB; *(uint32_t*)&Ol[o1] = lB;
    }
}

// =============================================================================
extern "C" void kernel_launch(void* const* d_in, const int* in_sizes, int n_in,
                              void* d_out, int out_size)
{
    const float* hidden = (const float*)d_in[0];
    const int* pos      = (const int*)d_in[1];
    const float* Wq     = (const float*)d_in[2];
    const float* Wk     = (const float*)d_in[3];
    const float* Wv     = (const float*)d_in[4];
    const float* Wo     = (const float*)d_in[5];
    const float* qw     = (const float*)d_in[6];
    const float* kw     = (const float*)d_in[7];
    const float* cosT   = (const float*)d_in[8];
    const float* sinT   = (const float*)d_in[9];
    float* out = (float*)d_out;

    float *qlin, *klin, *vlin;
    cudaGetSymbolAddress((void**)&qlin, g_qlin);
    cudaGetSymbolAddress((void**)&klin, g_klin);
    cudaGetSymbolAddress((void**)&vlin, g_vlin);

    bf16 *hid_hi, *hid_lo, *wq_hi, *wq_lo, *wk_hi, *wk_lo, *wv_hi, *wv_lo;
    bf16 *wo_hi, *wo_lo, *at_hi, *at_lo;
    bf16 *qh, *ql, *kh, *kl, *vth, *vtl;
    cudaGetSymbolAddress((void**)&hid_hi, g_hid_hi);
    cudaGetSymbolAddress((void**)&hid_lo, g_hid_lo);
    cudaGetSymbolAddress((void**)&wq_hi, g_wq_hi);
    cudaGetSymbolAddress((void**)&wq_lo, g_wq_lo);
    cudaGetSymbolAddress((void**)&wk_hi, g_wk_hi);
    cudaGetSymbolAddress((void**)&wk_lo, g_wk_lo);
    cudaGetSymbolAddress((void**)&wv_hi, g_wv_hi);
    cudaGetSymbolAddress((void**)&wv_lo, g_wv_lo);
    cudaGetSymbolAddress((void**)&wo_hi, g_wo_hi);
    cudaGetSymbolAddress((void**)&wo_lo, g_wo_lo);
    cudaGetSymbolAddress((void**)&at_hi, g_attn_hi);
    cudaGetSymbolAddress((void**)&at_lo, g_attn_lo);
    cudaGetSymbolAddress((void**)&qh, g_qh);
    cudaGetSymbolAddress((void**)&ql, g_ql);
    cudaGetSymbolAddress((void**)&kh, g_kh);
    cudaGetSymbolAddress((void**)&kl, g_kl);
    cudaGetSymbolAddress((void**)&vth, g_vth);
    cudaGetSymbolAddress((void**)&vtl, g_vtl);

    cudaFuncSetAttribute(hmma_gemm, cudaFuncAttributeMaxDynamicSharedMemorySize,
                         GEMM_SMEM_BYTES);
    cudaFuncSetAttribute(attn_hmma, cudaFuncAttributeMaxDynamicSharedMemorySize,
                         AT_SMEM);

    // split conversions
    {
        int n4;
        n4 = S_LEN * HID / 4;
        cvt_hilo<<<(n4 + 255) / 256, 256>>>((const float4*)hidden,
            (__nv_bfloat162*)hid_hi, (__nv_bfloat162*)hid_lo, n4);
        n4 = HID * HID / 4;
        cvt_hilo<<<(n4 + 255) / 256, 256>>>((const float4*)Wq,
            (__nv_bfloat162*)wq_hi, (__nv_bfloat162*)wq_lo, n4);
        n4 = (NKV * HD) * HID / 4;
        cvt_hilo<<<(n4 + 255) / 256, 256>>>((const float4*)Wk,
            (__nv_bfloat162*)wk_hi, (__nv_bfloat162*)wk_lo, n4);
        cvt_hilo<<<(n4 + 255) / 256, 256>>>((const float4*)Wv,
            (__nv_bfloat162*)wv_hi, (__nv_bfloat162*)wv_lo, n4);
        n4 = HID * HID / 4;
        cvt_hilo<<<(n4 + 255) / 256, 256>>>((const float4*)Wo,
            (__nv_bfloat162*)wo_hi, (__nv_bfloat162*)wo_lo, n4);
    }

    // projections (HMMA)
    hmma_gemm<<<dim3(HID / 128, S_LEN / 128), 256, GEMM_SMEM_BYTES>>>(
        hid_hi, hid_lo, wq_hi, wq_lo, qlin, S_LEN, HID, HID);
    hmma_gemm<<<dim3((NKV * HD) / 128, S_LEN / 128), 256, GEMM_SMEM_BYTES>>>(
        hid_hi, hid_lo, wk_hi, wk_lo, klin, S_LEN, NKV * HD, HID);
    hmma_gemm<<<dim3((NKV * HD) / 128, S_LEN / 128), 256, GEMM_SMEM_BYTES>>>(
        hid_hi, hid_lo, wv_hi, wv_lo, vlin, S_LEN, NKV * HD, HID);

    // RMSNorm + RoPE -> bf16 hi/lo ; V transpose+split
    qk_norm_rope<<<dim3(S_LEN, NH + NKV), 128>>>(qlin, klin, qw, kw, pos, cosT, sinT,
                                                 qh, ql, kh, kl);
    vt_cvt<<<dim3(S_LEN / 32, (NKV * HD) / 32), dim3(32, 8)>>>(vlin, vth, vtl);

    // HMMA flash attention -> bf16 hi/lo
    attn_hmma<<<dim3(S_LEN / 128, NH), 256, AT_SMEM>>>(qh, ql, kh, kl, vth, vtl,
                                                       at_hi, at_lo);

    // output projection (HMMA)
    hmma_gemm<<<dim3(HID / 128, S_LEN / 128), 256, GEMM_SMEM_BYTES>>>(
        at_hi, at_lo, wo_hi, wo_lo, out, S_LEN, HID, HID);
}

// round 13
// speedup vs baseline: 1.5401x; 1.5401x over previous
#include <cuda_runtime.h>
#include <cuda_bf16.h>
#include <cstdint>

typedef __nv_bfloat16 bf16;

#define S_LEN 2048
#define HID   4096
#define NH    32
#define NKV   8
#define HD    128
#define QKV_N 6144          // 4096 (Q) + 1024 (K) + 1024 (V)

// ---------------- scratch (static device globals; no allocation) -------------
__device__ __align__(256) float g_qkvlin[(size_t)S_LEN * QKV_N];   // [S][6144]

// split-bf16 buffers
__device__ __align__(256) bf16 g_hid_hi[(size_t)S_LEN * HID];
__device__ __align__(256) bf16 g_hid_lo[(size_t)S_LEN * HID];
__device__ __align__(256) bf16 g_wqkv_hi[(size_t)QKV_N * HID];     // rows: Wq|Wk|Wv
__device__ __align__(256) bf16 g_wqkv_lo[(size_t)QKV_N * HID];
__device__ __align__(256) bf16 g_wo_hi[(size_t)HID * HID];
__device__ __align__(256) bf16 g_wo_lo[(size_t)HID * HID];
__device__ __align__(256) bf16 g_attn_hi[(size_t)S_LEN * HID];
__device__ __align__(256) bf16 g_attn_lo[(size_t)S_LEN * HID];

// attention operands (hi/lo bf16)
__device__ __align__(256) bf16 g_qh[(size_t)NH * S_LEN * HD];
__device__ __align__(256) bf16 g_ql[(size_t)NH * S_LEN * HD];
__device__ __align__(256) bf16 g_kh[(size_t)NKV * S_LEN * HD];
__device__ __align__(256) bf16 g_kl[(size_t)NKV * S_LEN * HD];
__device__ __align__(256) bf16 g_vth[(size_t)NKV * HD * S_LEN];    // [kvh*128+d][s]
__device__ __align__(256) bf16 g_vtl[(size_t)NKV * HD * S_LEN];

// ============================= helpers ======================================
__device__ __forceinline__ uint32_t smem_u32(const void* p) {
    uint32_t a;
    asm("{ .reg .u64 t; cvta.to.shared.u64 t, %1; cvt.u32.u64 %0, t; }"
        : "=r"(a) : "l"(p));
    return a;
}

#define SW128(o) ((o) ^ (((o) >> 3) & 0x70))

__device__ __forceinline__ void cpasync16(uint32_t dst, const void* src) {
    asm volatile("cp.async.cg.shared.global [%0], [%1], 16;"
                 :: "r"(dst), "l"(src));
}

#define LDSM4(r0, r1, r2, r3, a)                                              \
    asm volatile("ldmatrix.sync.aligned.m8n8.x4.shared.b16 {%0,%1,%2,%3}, [%4];" \
        : "=r"(r0), "=r"(r1), "=r"(r2), "=r"(r3) : "r"(a))

#define MMA16816(d, a0, a1, a2, a3, b0, b1)                                   \
    asm volatile("mma.sync.aligned.m16n8k16.row.col.f32.bf16.bf16.f32 "       \
        "{%0,%1,%2,%3}, {%4,%5,%6,%7}, {%8,%9}, {%0,%1,%2,%3};"               \
        : "+f"((d)[0]), "+f"((d)[1]), "+f"((d)[2]), "+f"((d)[3])              \
        : "r"(a0), "r"(a1), "r"(a2), "r"(a3), "r"(b0), "r"(b1))

__device__ __forceinline__ uint32_t pack2(bf16 a, bf16 b) {
    __nv_bfloat162 t = __halves2bfloat162(a, b);
    return *reinterpret_cast<uint32_t*>(&t);
}

__device__ __forceinline__ void psplit(float a, float b, uint32_t& hi, uint32_t& lo) {
    bf16 ha = __float2bfloat16(a), hb = __float2bfloat16(b);
    float ra = a - __bfloat162float(ha), rb = b - __bfloat162float(hb);
    hi = pack2(ha, hb);
    lo = pack2(__float2bfloat16(ra), __float2bfloat16(rb));
}

// ============================================================================
// fp32 -> (bf16 hi, bf16 lo) split conversion, vectorized x4
// ============================================================================
__global__ __launch_bounds__(256) void cvt_hilo(
    const float4* __restrict__ x, __nv_bfloat162* __restrict__ hi,
    __nv_bfloat162* __restrict__ lo, int n4)
{
    int i = blockIdx.x * 256 + threadIdx.x;
    if (i >= n4) return;
    float4 v = x[i];
    bf16 h0 = __float2bfloat16(v.x), h1 = __float2bfloat16(v.y);
    bf16 h2 = __float2bfloat16(v.z), h3 = __float2bfloat16(v.w);
    bf16 l0 = __float2bfloat16(v.x - __bfloat162float(h0));
    bf16 l1 = __float2bfloat16(v.y - __bfloat162float(h1));
    bf16 l2 = __float2bfloat16(v.z - __bfloat162float(h2));
    bf16 l3 = __float2bfloat16(v.w - __bfloat162float(h3));
    hi[2 * i]     = __halves2bfloat162(h0, h1);
    hi[2 * i + 1] = __halves2bfloat162(h2, h3);
    lo[2 * i]     = __halves2bfloat162(l0, l1);
    lo[2 * i + 1] = __halves2bfloat162(l2, l3);
}

// ============================================================================
// V transpose + split: qkvlin[:, 5120:6144] fp32 -> vt_hi/lo [kvh*128+d][S]
// ============================================================================
__global__ __launch_bounds__(256) void vt_cvt(
    const float* __restrict__ v, bf16* __restrict__ th, bf16* __restrict__ tl)
{
    __shared__ float t[32][33];
    int s0 = blockIdx.x * 32, c0 = blockIdx.y * 32;
    int tx = threadIdx.x, ty = threadIdx.y;
    #pragma unroll
    for (int r = 0; r < 4; r++)
        t[ty + r * 8][tx] = v[(size_t)(s0 + ty + r * 8) * QKV_N + c0 + tx];
    __syncthreads();
    #pragma unroll
    for (int r = 0; r < 4; r++) {
        int gc = c0 + ty + r * 8;
        float val = t[tx][ty + r * 8];
        bf16 hh = __float2bfloat16(val);
        bf16 ll = __float2bfloat16(val - __bfloat162float(hh));
        th[(size_t)gc * S_LEN + s0 + tx] = hh;
        tl[(size_t)gc * S_LEN + s0 + tx] = ll;
    }
}

// ============================================================================
// HMMA split-bf16 GEMM (R10-proven 2-stage double buffer, 2 syncs/iter)
// CTA 128x128, BK=64, 8 warps (2x4), warp tile 64x32, SW128 smem.
// ============================================================================
#define GS_A  16384u
#define GSTG  65536u
#define GEMM_SMEM_BYTES (2 * 65536)

__global__ __launch_bounds__(256) void hmma_gemm(
    const bf16* __restrict__ Ah, const bf16* __restrict__ Al,
    const bf16* __restrict__ Bh, const bf16* __restrict__ Bl,
    float* __restrict__ C, int M, int N, int K)
{
    extern __shared__ char smc[];
    uint32_t sb = smem_u32(smc);

    int tid = threadIdx.x;
    int wid = tid >> 5, lane = tid & 31;
    int mbase = blockIdx.y * 128, nbase = blockIdx.x * 128;
    int warpM = (wid & 1) * 64;
    int warpN = (wid >> 1) * 32;

    const bf16* Aho = Ah + (size_t)mbase * K;
    const bf16* Alo = Al + (size_t)mbase * K;
    const bf16* Bho = Bh + (size_t)nbase * K;
    const bf16* Blo = Bl + (size_t)nbase * K;

    const int KT = K >> 6;

    auto load_stage = [&](int s, int kt) {
        uint32_t sa = sb + (uint32_t)s * GSTG;
        int kb = kt << 6;
        #pragma unroll
        for (int i = 0; i < 4; i++) {
            int idx = tid + i * 256;
            int row = idx >> 3;
            int c8 = idx & 7;
            uint32_t off = SW128((uint32_t)(row * 128 + c8 * 16));
            size_t g = (size_t)row * K + kb + c8 * 8;
            cpasync16(sa + off,              Aho + g);
            cpasync16(sa + GS_A + off,       Alo + g);
            cpasync16(sa + 2 * GS_A + off,   Bho + g);
            cpasync16(sa + 3 * GS_A + off,   Blo + g);
        }
        asm volatile("cp.async.commit_group;" ::: "memory");
    };

    float acc[4][4][4];
    #pragma unroll
    for (int a = 0; a < 4; a++)
        #pragma unroll
        for (int b = 0; b < 4; b++)
            #pragma unroll
            for (int c = 0; c < 4; c++) acc[a][b][c] = 0.f;

    load_stage(0, 0);

    uint32_t lrow = lane & 15;
    uint32_t lcsel = (lane >> 4) * 16;

    for (int kt = 0; kt < KT; kt++) {
        if (kt + 1 < KT) {
            load_stage((kt + 1) & 1, kt + 1);
            asm volatile("cp.async.wait_group 1;" ::: "memory");
        } else {
            asm volatile("cp.async.wait_group 0;" ::: "memory");
        }
        __syncthreads();

        uint32_t st = sb + (uint32_t)(kt & 1) * GSTG;
        #pragma unroll
        for (int kk = 0; kk < 4; kk++) {
            uint32_t acol = kk * 32 + lcsel;
            uint32_t ah4[4][4], al4[4][4];
            #pragma unroll
            for (int mi = 0; mi < 4; mi++) {
                uint32_t off = SW128((uint32_t)((warpM + mi * 16 + lrow) * 128) + acol);
                LDSM4(ah4[mi][0], ah4[mi][1], ah4[mi][2], ah4[mi][3], st + off);
                LDSM4(al4[mi][0], al4[mi][1], al4[mi][2], al4[mi][3], st + GS_A + off);
            }
            uint32_t bh4[2][4], bl4[2][4];
            #pragma unroll
            for (int p = 0; p < 2; p++) {
                uint32_t off = SW128((uint32_t)((warpN + p * 16 + lrow) * 128) + acol);
                LDSM4(bh4[p][0], bh4[p][1], bh4[p][2], bh4[p][3], st + 2 * GS_A + off);
                LDSM4(bl4[p][0], bl4[p][1], bl4[p][2], bl4[p][3], st + 3 * GS_A + off);
            }
            #pragma unroll
            for (int mi = 0; mi < 4; mi++) {
                #pragma unroll
                for (int t = 0; t < 4; t++) {
                    int p = t >> 1, h = t & 1;
                    MMA16816(acc[mi][t], ah4[mi][0], ah4[mi][1], ah4[mi][2], ah4[mi][3],
                             bh4[p][h], bh4[p][h + 2]);
                    MMA16816(acc[mi][t], ah4[mi][0], ah4[mi][1], ah4[mi][2], ah4[mi][3],
                             bl4[p][h], bl4[p][h + 2]);
                    MMA16816(acc[mi][t], al4[mi][0], al4[mi][1], al4[mi][2], al4[mi][3],
                             bh4[p][h], bh4[p][h + 2]);
                }
            }
        }
        __syncthreads();
    }

    #pragma unroll
    for (int mi = 0; mi < 4; mi++) {
        int row0 = mbase + warpM + mi * 16 + (lane >> 2);
        #pragma unroll
        for (int t = 0; t < 4; t++) {
            int col = nbase + warpN + t * 8 + (lane & 3) * 2;
            float2 v0 = { acc[mi][t][0], acc[mi][t][1] };
            float2 v1 = { acc[mi][t][2], acc[mi][t][3] };
            *(float2*)&C[(size_t)row0 * N + col] = v0;
            *(float2*)&C[(size_t)(row0 + 8) * N + col] = v1;
        }
    }
}

// =============================================================================
// Per-(s, head) RMSNorm + RoPE -> bf16 hi/lo head-major (reads fused qkvlin)
// =============================================================================
__global__ __launch_bounds__(128) void qk_norm_rope(
    const float* __restrict__ qkv,
    const float* __restrict__ qw, const float* __restrict__ kw,
    const int* __restrict__ pos_ids,
    const float* __restrict__ cosT, const float* __restrict__ sinT,
    bf16* __restrict__ qh, bf16* __restrict__ ql,
    bf16* __restrict__ kh, bf16* __restrict__ kl)
{
    int s = blockIdx.x;
    int hb = blockIdx.y;
    int i = threadIdx.x;

    float x;
    const float* w;
    bf16 *dh, *dl;
    size_t o;
    if (hb < NH) {
        x = qkv[(size_t)s * QKV_N + hb * HD + i];
        w = qw;
        o = ((size_t)hb * S_LEN + s) * HD + i;
        dh = qh; dl = ql;
    } else {
        int hk = hb - NH;
        x = qkv[(size_t)s * QKV_N + HID + hk * HD + i];
        w = kw;
        o = ((size_t)hk * S_LEN + s) * HD + i;
        dh = kh; dl = kl;
    }

    __shared__ float red[128];
    __shared__ float xs[128];
    __shared__ float s_inv;

    red[i] = x * x;
    __syncthreads();
    if (i < 64) red[i] += red[i + 64];
    __syncthreads();
    if (i < 32) {
        float v = red[i] + red[i + 32];
        #pragma unroll
        for (int of = 16; of > 0; of >>= 1) v += __shfl_xor_sync(0xffffffffu, v, of);
        if (i == 0) s_inv = rsqrtf(v * (1.0f / 128.0f) + 1e-6f);
    }
    __syncthreads();

    float xn = x * s_inv * w[i];
    xs[i] = xn;
    __syncthreads();
    float other = (i < 64) ? -xs[i + 64] : xs[i - 64];
    int p = pos_ids[s];
    float c = cosT[(size_t)p * HD + i];
    float sn = sinT[(size_t)p * HD + i];
    float r = xn * c + other * sn;
    bf16 hh = __float2bfloat16(r);
    dh[o] = hh;
    dl[o] = __float2bfloat16(r - __bfloat162float(hh));
}

// =============================================================================
// HMMA flash attention (split-bf16, causal, GQA 4:1) — R10 structure + qb rev.
// =============================================================================
#define AT_SMEM 196608

__global__ __launch_bounds__(256) void attn_hmma(
    const bf16* __restrict__ Qh, const bf16* __restrict__ Ql,
    const bf16* __restrict__ Kh, const bf16* __restrict__ Kl,
    const bf16* __restrict__ Vh, const bf16* __restrict__ Vl,
    bf16* __restrict__ Oh, bf16* __restrict__ Ol)
{
    extern __shared__ char smc[];
    uint32_t sb = smem_u32(smc);
    const uint32_t QHo = 0, QLo = 32768, STG0 = 65536, STGSZ = 65536;

    int h = blockIdx.y;
    int qb = gridDim.x - 1 - blockIdx.x;   // heavy CTAs dispatch first
    int kvh = h >> 2;
    int qbase = qb * 128;
    int tid = threadIdx.x, wid = tid >> 5, lane = tid & 31;
    int warpM = wid * 16;

    // Q loads (bundled into first commit group with kv stage 0)
    const bf16* qhs = Qh + ((size_t)h * S_LEN + qbase) * HD;
    const bf16* qls = Ql + ((size_t)h * S_LEN + qbase) * HD;
    #pragma unroll
    for (int i = 0; i < 8; i++) {
        int idx = tid + i * 256;
        int c = idx >> 10, rem = idx & 1023;
        int row = rem >> 3, c8 = rem & 7;
        uint32_t off = (uint32_t)c * 16384u + SW128((uint32_t)(row * 128 + c8 * 16));
        size_t g = (size_t)row * HD + c * 64 + c8 * 8;
        cpasync16(sb + QHo + off, qhs + g);
        cpasync16(sb + QLo + off, qls + g);
    }

    auto load_kv = [&](int st, int kt) {
        uint32_t sa = sb + STG0 + (uint32_t)st * STGSZ;
        int n0 = kt * 64;
        const bf16* khs = Kh + ((size_t)kvh * S_LEN + n0) * HD;
        const bf16* kls = Kl + ((size_t)kvh * S_LEN + n0) * HD;
        #pragma unroll
        for (int i = 0; i < 4; i++) {
            int idx = tid + i * 256;
            int c = idx >> 9, row = (idx >> 3) & 63, c8 = idx & 7;
            uint32_t off = (uint32_t)c * 8192u + SW128((uint32_t)(row * 128 + c8 * 16));
            size_t g = (size_t)row * HD + c * 64 + c8 * 8;
            cpasync16(sa + off, khs + g);
            cpasync16(sa + 16384u + off, kls + g);
        }
        const bf16* vhs = Vh + (size_t)kvh * HD * S_LEN + n0;
        const bf16* vls = Vl + (size_t)kvh * HD * S_LEN + n0;
        #pragma unroll
        for (int i = 0; i < 4; i++) {
            int idx = tid + i * 256;
            int row = idx >> 3, c8 = idx & 7;
            uint32_t off = SW128((uint32_t)(row * 128 + c8 * 16));
            size_t g = (size_t)row * S_LEN + c8 * 8;
            cpasync16(sa + 32768u + off, vhs + g);
            cpasync16(sa + 49152u + off, vls + g);
        }
        asm volatile("cp.async.commit_group;" ::: "memory");
    };

    load_kv(0, 0);

    float acc_o[16][4];
    #pragma unroll
    for (int n = 0; n < 16; n++)
        #pragma unroll
        for (int c = 0; c < 4; c++) acc_o[n][c] = 0.f;
    float m0 = -1e30f, m1 = -1e30f, l0 = 0.f, l1 = 0.f;

    int nkt = 2 * (qb + 1);
    const float scale = 0.08838834764831845f;
    uint32_t lrow = lane & 15, lcsel = (lane >> 4) * 16;
    int rowg0 = qbase + warpM + (lane >> 2);

    for (int kt = 0; kt < nkt; kt++) {
        if (kt + 1 < nkt) {
            load_kv((kt + 1) & 1, kt + 1);
            asm volatile("cp.async.wait_group 1;" ::: "memory");
        } else {
            asm volatile("cp.async.wait_group 0;" ::: "memory");
        }
        __syncthreads();
        uint32_t sa = sb + STG0 + (uint32_t)(kt & 1) * STGSZ;
        int n0 = kt * 64;

        // ---- S = Q K^T (3-term split)
        float acc_s[8][4];
        #pragma unroll
        for (int n = 0; n < 8; n++)
            #pragma unroll
            for (int c = 0; c < 4; c++) acc_s[n][c] = 0.f;

        #pragma unroll
        for (int c = 0; c < 2; c++) {
            #pragma unroll
            for (int kk = 0; kk < 4; kk++) {
                uint32_t aoff = (uint32_t)c * 16384u +
                    SW128((uint32_t)((warpM + lrow) * 128) + kk * 32 + lcsel);
                uint32_t aH[4], aL[4];
                LDSM4(aH[0], aH[1], aH[2], aH[3], sb + QHo + aoff);
                LDSM4(aL[0], aL[1], aL[2], aL[3], sb + QLo + aoff);
                #pragma unroll
                for (int kg = 0; kg < 4; kg++) {
                    uint32_t boff = (uint32_t)c * 8192u +
                        SW128((uint32_t)((kg * 16 + lrow) * 128) + kk * 32 + lcsel);
                    uint32_t bH[4], bL[4];
                    LDSM4(bH[0], bH[1], bH[2], bH[3], sa + boff);
                    LDSM4(bL[0], bL[1], bL[2], bL[3], sa + 16384u + boff);
                    #pragma unroll
                    for (int hh = 0; hh < 2; hh++) {
                        int nt = kg * 2 + hh;
                        MMA16816(acc_s[nt], aH[0], aH[1], aH[2], aH[3], bH[hh], bH[hh + 2]);
                        MMA16816(acc_s[nt], aH[0], aH[1], aH[2], aH[3], bL[hh], bL[hh + 2]);
                        MMA16816(acc_s[nt], aL[0], aL[1], aL[2], aL[3], bH[hh], bH[hh + 2]);
                    }
                }
            }
        }

        // ---- scale + causal mask
        bool anymask = (n0 + 64 > qbase + warpM);
        #pragma unroll
        for (int nt = 0; nt < 8; nt++) {
            #pragma unroll
            for (int c = 0; c < 4; c++) acc_s[nt][c] *= scale;
        }
        if (anymask) {
            #pragma unroll
            for (int nt = 0; nt < 8; nt++) {
                int colb = n0 + nt * 8 + (lane & 3) * 2;
                if (colb > rowg0)         acc_s[nt][0] = -1e30f;
                if (colb + 1 > rowg0)     acc_s[nt][1] = -1e30f;
                if (colb > rowg0 + 8)     acc_s[nt][2] = -1e30f;
                if (colb + 1 > rowg0 + 8) acc_s[nt][3] = -1e30f;
            }
        }

        // ---- online softmax
        float mx0 = -1e30f, mx1 = -1e30f;
        #pragma unroll
        for (int nt = 0; nt < 8; nt++) {
            mx0 = fmaxf(mx0, fmaxf(acc_s[nt][0], acc_s[nt][1]));
            mx1 = fmaxf(mx1, fmaxf(acc_s[nt][2], acc_s[nt][3]));
        }
        mx0 = fmaxf(mx0, __shfl_xor_sync(0xffffffffu, mx0, 1));
        mx0 = fmaxf(mx0, __shfl_xor_sync(0xffffffffu, mx0, 2));
        mx1 = fmaxf(mx1, __shfl_xor_sync(0xffffffffu, mx1, 1));
        mx1 = fmaxf(mx1, __shfl_xor_sync(0xffffffffu, mx1, 2));
        float mn0 = fmaxf(m0, mx0), mn1 = fmaxf(m1, mx1);
        float al0 = __expf(m0 - mn0), al1 = __expf(m1 - mn1);

        float s0 = 0.f, s1 = 0.f;
        #pragma unroll
        for (int nt = 0; nt < 8; nt++) {
            acc_s[nt][0] = __expf(acc_s[nt][0] - mn0);
            acc_s[nt][1] = __expf(acc_s[nt][1] - mn0);
            acc_s[nt][2] = __expf(acc_s[nt][2] - mn1);
            acc_s[nt][3] = __expf(acc_s[nt][3] - mn1);
            s0 += acc_s[nt][0] + acc_s[nt][1];
            s1 += acc_s[nt][2] + acc_s[nt][3];
        }
        s0 += __shfl_xor_sync(0xffffffffu, s0, 1);
        s0 += __shfl_xor_sync(0xffffffffu, s0, 2);
        s1 += __shfl_xor_sync(0xffffffffu, s1, 1);
        s1 += __shfl_xor_sync(0xffffffffu, s1, 2);
        l0 = l0 * al0 + s0; m0 = mn0;
        l1 = l1 * al1 + s1; m1 = mn1;

        // ---- pack P into PV A-fragments (registers only)
        uint32_t paH[4][4], paL[4][4];
        #pragma unroll
        for (int k2 = 0; k2 < 4; k2++) {
            int a = 2 * k2, b = 2 * k2 + 1;
            psplit(acc_s[a][0], acc_s[a][1], paH[k2][0], paL[k2][0]);
            psplit(acc_s[a][2], acc_s[a][3], paH[k2][1], paL[k2][1]);
            psplit(acc_s[b][0], acc_s[b][1], paH[k2][2], paL[k2][2]);
            psplit(acc_s[b][2], acc_s[b][3], paH[k2][3], paL[k2][3]);
        }

        // ---- rescale O
        #pragma unroll
        for (int nt = 0; nt < 16; nt++) {
            acc_o[nt][0] *= al0; acc_o[nt][1] *= al0;
            acc_o[nt][2] *= al1; acc_o[nt][3] *= al1;
        }

        // ---- O += P V (3-term split)
        #pragma unroll
        for (int k2 = 0; k2 < 4; k2++) {
            #pragma unroll
            for (int dg = 0; dg < 8; dg++) {
                uint32_t boff = SW128((uint32_t)((dg * 16 + lrow) * 128) + k2 * 32 + lcsel);
                uint32_t bH[4], bL[4];
                LDSM4(bH[0], bH[1], bH[2], bH[3], sa + 32768u + boff);
                LDSM4(bL[0], bL[1], bL[2], bL[3], sa + 49152u + boff);
                #pragma unroll
                for (int hh = 0; hh < 2; hh++) {
                    int nt = dg * 2 + hh;
                    MMA16816(acc_o[nt], paH[k2][0], paH[k2][1], paH[k2][2], paH[k2][3],
                             bH[hh], bH[hh + 2]);
                    MMA16816(acc_o[nt], paH[k2][0], paH[k2][1], paH[k2][2], paH[k2][3],
                             bL[hh], bL[hh + 2]);
                    MMA16816(acc_o[nt], paL[k2][0], paL[k2][1], paL[k2][2], paL[k2][3],
                             bH[hh], bH[hh + 2]);
                }
            }
        }
        __syncthreads();
    }

    // ---- epilogue: write bf16 hi/lo directly
    float inv0 = 1.0f / l0, inv1 = 1.0f / l1;
    #pragma unroll
    for (int nt = 0; nt < 16; nt++) {
        int col = h * HD + nt * 8 + (lane & 3) * 2;
        float v0 = acc_o[nt][0] * inv0, v1 = acc_o[nt][1] * inv0;
        float v2 = acc_o[nt][2] * inv1, v3 = acc_o[nt][3] * inv1;
        uint32_t hA, lA, hB, lB;
        psplit(v0, v1, hA, lA);
        psplit(v2, v3, hB, lB);
        size_t o0 = (size_t)rowg0 * HID + col;
        size_t o1 = (size_t)(rowg0 + 8) * HID + col;
        *(uint32_t*)&Oh[o0] = hA; *(uint32_t*)&Ol[o0] = lA;
        *(uint32_t*)&Oh[o1] = hB; *(uint32_t*)&Ol[o1] = lB;
    }
}

// =============================================================================
extern "C" void kernel_launch(void* const* d_in, const int* in_sizes, int n_in,
                              void* d_out, int out_size)
{
    const float* hidden = (const float*)d_in[0];
    const int* pos      = (const int*)d_in[1];
    const float* Wq     = (const float*)d_in[2];
    const float* Wk     = (const float*)d_in[3];
    const float* Wv     = (const float*)d_in[4];
    const float* Wo     = (const float*)d_in[5];
    const float* qw     = (const float*)d_in[6];
    const float* kw     = (const float*)d_in[7];
    const float* cosT   = (const float*)d_in[8];
    const float* sinT   = (const float*)d_in[9];
    float* out = (float*)d_out;

    float* qkvlin;
    cudaGetSymbolAddress((void**)&qkvlin, g_qkvlin);

    bf16 *hid_hi, *hid_lo, *wqkv_hi, *wqkv_lo, *wo_hi, *wo_lo, *at_hi, *at_lo;
    bf16 *qh, *ql, *kh, *kl, *vth, *vtl;
    cudaGetSymbolAddress((void**)&hid_hi, g_hid_hi);
    cudaGetSymbolAddress((void**)&hid_lo, g_hid_lo);
    cudaGetSymbolAddress((void**)&wqkv_hi, g_wqkv_hi);
    cudaGetSymbolAddress((void**)&wqkv_lo, g_wqkv_lo);
    cudaGetSymbolAddress((void**)&wo_hi, g_wo_hi);
    cudaGetSymbolAddress((void**)&wo_lo, g_wo_lo);
    cudaGetSymbolAddress((void**)&at_hi, g_attn_hi);
    cudaGetSymbolAddress((void**)&at_lo, g_attn_lo);
    cudaGetSymbolAddress((void**)&qh, g_qh);
    cudaGetSymbolAddress((void**)&ql, g_ql);
    cudaGetSymbolAddress((void**)&kh, g_kh);
    cudaGetSymbolAddress((void**)&kl, g_kl);
    cudaGetSymbolAddress((void**)&vth, g_vth);
    cudaGetSymbolAddress((void**)&vtl, g_vtl);

    cudaFuncSetAttribute(hmma_gemm, cudaFuncAttributeMaxDynamicSharedMemorySize,
                         GEMM_SMEM_BYTES);
    cudaFuncSetAttribute(attn_hmma, cudaFuncAttributeMaxDynamicSharedMemorySize,
                         AT_SMEM);

    // split conversions (weights fused into one [6144,4096] block: Wq|Wk|Wv)
    {
        int n4;
        n4 = S_LEN * HID / 4;
        cvt_hilo<<<(n4 + 255) / 256, 256>>>((const float4*)hidden,
            (__nv_bfloat162*)hid_hi, (__nv_bfloat162*)hid_lo, n4);
        n4 = HID * HID / 4;
        cvt_hilo<<<(n4 + 255) / 256, 256>>>((const float4*)Wq,
            (__nv_bfloat162*)wqkv_hi, (__nv_bfloat162*)wqkv_lo, n4);
        n4 = (NKV * HD) * HID / 4;
        cvt_hilo<<<(n4 + 255) / 256, 256>>>((const float4*)Wk,
            (__nv_bfloat162*)(wqkv_hi + (size_t)HID * HID),
            (__nv_bfloat162*)(wqkv_lo + (size_t)HID * HID), n4);
        cvt_hilo<<<(n4 + 255) / 256, 256>>>((const float4*)Wv,
            (__nv_bfloat162*)(wqkv_hi + (size_t)(HID + NKV * HD) * HID),
            (__nv_bfloat162*)(wqkv_lo + (size_t)(HID + NKV * HD) * HID), n4);
        n4 = HID * HID / 4;
        cvt_hilo<<<(n4 + 255) / 256, 256>>>((const float4*)Wo,
            (__nv_bfloat162*)wo_hi, (__nv_bfloat162*)wo_lo, n4);
    }

    // fused QKV projection (HMMA): [2048, 6144] = hid @ [Wq|Wk|Wv]^T
    hmma_gemm<<<dim3(QKV_N / 128, S_LEN / 128), 256, GEMM_SMEM_BYTES>>>(
        hid_hi, hid_lo, wqkv_hi, wqkv_lo, qkvlin, S_LEN, QKV_N, HID);

    // RMSNorm + RoPE -> bf16 hi/lo ; V transpose+split (reads fused buffer)
    qk_norm_rope<<<dim3(S_LEN, NH + NKV), 128>>>(qkvlin, qw, kw, pos, cosT, sinT,
                                                 qh, ql, kh, kl);
    vt_cvt<<<dim3(S_LEN / 32, (NKV * HD) / 32), dim3(32, 8)>>>(
        qkvlin + (size_t)(HID + NKV * HD), vth, vtl);

    // HMMA flash attention -> bf16 hi/lo
    attn_hmma<<<dim3(S_LEN / 128, NH), 256, AT_SMEM>>>(qh, ql, kh, kl, vth, vtl,
                                                       at_hi, at_lo);

    // output projection (HMMA)
    hmma_gemm<<<dim3(HID / 128, S_LEN / 128), 256, GEMM_SMEM_BYTES>>>(
        at_hi, at_lo, wo_hi, wo_lo, out, S_LEN, HID, HID);
}